// round 9
// baseline (speedup 1.0000x reference)
#include <cuda_runtime.h>
#include <math.h>

// Problem constants
//   x: [2, 2048, 1024] -> rows M=4096
//   Q_PROJ = KV_PROJ = 256, N_HEADS=16, DH=64
// Pipeline:
//   cdown = x @ [W_dq | W_dkv]          [4096, 512]
//   cln   = LN(cdown) per 256-half      [4096, 512]
//   Q     = cln[:, :256] @ W_uq         [4096, 1024]
//   KV    = cln[:, 256:] @ W_ukv        [4096, 2048]   (K = cols 0..1023, V = 1024..2047)
//   O     = causal_attention(Q, K, V)   [4096, 1024]
//   out   = O @ W_o^T                   [4096, 1024]

// -------------------- scratch (device globals; no allocation) --------------------
__device__ float g_cdown[4096 * 512];
__device__ float g_cln  [4096 * 512];
__device__ float g_Q    [4096 * 1024];
__device__ float g_KV   [4096 * 2048];
__device__ float g_O    [4096 * 1024];

// -------------------- helpers --------------------
__device__ __forceinline__ float warp_sum32(float v) {
    v += __shfl_xor_sync(0xffffffffu, v, 16);
    v += __shfl_xor_sync(0xffffffffu, v, 8);
    v += __shfl_xor_sync(0xffffffffu, v, 4);
    v += __shfl_xor_sync(0xffffffffu, v, 2);
    v += __shfl_xor_sync(0xffffffffu, v, 1);
    return v;
}

// -------------------- generic tiled SGEMM: C[M,N] = A[M,K] @ B(K,N) --------------------
// BM=BN=128, BK=8, 256 threads, 8x8 microtile (split 4+4 halves for conflict-free LDS.128).
// TRANSB=false: B is row-major [K,N].  TRANSB=true: C = A @ B^T with B row-major [N,K].
template <bool TRANSB>
__global__ __launch_bounds__(256) void gemm_kernel(
    const float* __restrict__ A, const float* __restrict__ B, float* __restrict__ C,
    int K, int lda, int ldb, int ldc)
{
    __shared__ float As[8][128];   // As[k][m]
    __shared__ float Bs[8][128];   // Bs[k][n]

    const int t  = threadIdx.x;
    const int tx = t & 15;         // N direction
    const int ty = t >> 4;         // M direction
    const int m0 = blockIdx.y * 128;
    const int n0 = blockIdx.x * 128;

    float acc[8][8];
#pragma unroll
    for (int i = 0; i < 8; i++)
#pragma unroll
        for (int j = 0; j < 8; j++) acc[i][j] = 0.0f;

    const int am = t >> 1;            // 0..127
    const int ak = (t & 1) * 4;       // 0 or 4

    for (int k0 = 0; k0 < K; k0 += 8) {
        // load A tile (128 x 8), store transposed
        {
            float4 av = *(const float4*)&A[(size_t)(m0 + am) * lda + k0 + ak];
            As[ak + 0][am] = av.x;
            As[ak + 1][am] = av.y;
            As[ak + 2][am] = av.z;
            As[ak + 3][am] = av.w;
        }
        // load B tile (8 x 128)
        if (TRANSB) {
            const int j  = t >> 1;           // 0..127 (output col)
            const int kk = (t & 1) * 4;
            float4 bv = *(const float4*)&B[(size_t)(n0 + j) * ldb + k0 + kk];
            Bs[kk + 0][j] = bv.x;
            Bs[kk + 1][j] = bv.y;
            Bs[kk + 2][j] = bv.z;
            Bs[kk + 3][j] = bv.w;
        } else {
            const int kk = t >> 5;           // 0..7
            const int c  = (t & 31) * 4;     // 0..124
            float4 bv = *(const float4*)&B[(size_t)(k0 + kk) * ldb + n0 + c];
            *(float4*)&Bs[kk][c] = bv;
        }
        __syncthreads();

#pragma unroll
        for (int k = 0; k < 8; k++) {
            float4 a0 = *(const float4*)&As[k][ty * 4];
            float4 a1 = *(const float4*)&As[k][64 + ty * 4];
            float4 b0 = *(const float4*)&Bs[k][tx * 4];
            float4 b1 = *(const float4*)&Bs[k][64 + tx * 4];
            float a[8] = {a0.x, a0.y, a0.z, a0.w, a1.x, a1.y, a1.z, a1.w};
            float b[8] = {b0.x, b0.y, b0.z, b0.w, b1.x, b1.y, b1.z, b1.w};
#pragma unroll
            for (int i = 0; i < 8; i++)
#pragma unroll
                for (int j = 0; j < 8; j++) acc[i][j] += a[i] * b[j];
        }
        __syncthreads();
    }

    // store: rows {ty*4+i, 64+ty*4+i}, cols {tx*4+j, 64+tx*4+j}
#pragma unroll
    for (int i = 0; i < 8; i++) {
        int row = m0 + ((i < 4) ? (ty * 4 + i) : (64 + ty * 4 + (i - 4)));
        float4 c0 = make_float4(acc[i][0], acc[i][1], acc[i][2], acc[i][3]);
        float4 c1 = make_float4(acc[i][4], acc[i][5], acc[i][6], acc[i][7]);
        *(float4*)&C[(size_t)row * ldc + n0 + tx * 4]      = c0;
        *(float4*)&C[(size_t)row * ldc + n0 + 64 + tx * 4] = c1;
    }
}

// -------------------- layernorm over 256-element halves --------------------
// grid: (4096 rows, 2 halves), 256 threads
__global__ __launch_bounds__(256) void ln_kernel(
    const float* __restrict__ cd, float* __restrict__ cl,
    const float* __restrict__ qg, const float* __restrict__ qb,
    const float* __restrict__ kg, const float* __restrict__ kb)
{
    const int row  = blockIdx.x;
    const int half = blockIdx.y;
    const int tid  = threadIdx.x;
    const size_t idx = (size_t)row * 512 + half * 256 + tid;

    float v = cd[idx];

    __shared__ float red[8];
    float s = warp_sum32(v);
    if ((tid & 31) == 0) red[tid >> 5] = s;
    __syncthreads();
    float tot = 0.0f;
#pragma unroll
    for (int i = 0; i < 8; i++) tot += red[i];
    float mu = tot * (1.0f / 256.0f);
    float d  = v - mu;
    __syncthreads();

    float s2 = warp_sum32(d * d);
    if ((tid & 31) == 0) red[tid >> 5] = s2;
    __syncthreads();
    float var = 0.0f;
#pragma unroll
    for (int i = 0; i < 8; i++) var += red[i];
    var *= (1.0f / 256.0f);

    float inv = rsqrtf(var + 1e-5f);
    const float* g = half ? kg : qg;
    const float* b = half ? kb : qb;
    cl[idx] = d * inv * g[tid] + b[tid];
}

// -------------------- causal flash attention --------------------
// grid: (32 q-tiles, 32 b*h), 256 threads. BM=BN=64, DH=64.
// Thread (rg, cg): rows rg*4..+3, score cols / output dims cg*4..+3.
// smem pitch 68 (mult of 4 for float4 alignment; breaks 32-way transpose-store conflicts).
#define FA_P 68
#define FA_SMEM (4 * 64 * FA_P * 4)

__global__ __launch_bounds__(256) void flash_kernel(
    const float* __restrict__ Qb, const float* __restrict__ KVb, float* __restrict__ Ob)
{
    extern __shared__ float sm[];
    float* Qst = sm;                 // [d][r]  (transposed)
    float* Kst = sm + 64 * FA_P;     // [d][c]  (transposed)
    float* Vs  = sm + 2 * 64 * FA_P; // [c][d]
    float* Ps  = sm + 3 * 64 * FA_P; // [c][r]  (transposed probs)

    const int bh = blockIdx.y;
    const int b  = bh >> 4;
    const int h  = bh & 15;
    const int qt = blockIdx.x;

    const float* Qg = Qb  + ((size_t)(b * 2048 + qt * 64)) * 1024 + h * 64;
    const float* Kg = KVb + (size_t)b * 2048 * 2048 + h * 64;
    const float* Vg = Kg + 1024;
    float*       Og = Ob  + ((size_t)(b * 2048 + qt * 64)) * 1024 + h * 64;

    const int t = threadIdx.x;

    // load Q tile transposed, pre-scaled by 1/sqrt(64)
    for (int i = t; i < 4096; i += 256) {
        int r = i >> 6, c = i & 63;
        Qst[c * FA_P + r] = Qg[(size_t)r * 1024 + c] * 0.125f;
    }

    const int rg = t >> 4;          // row group 0..15
    const int cg = t & 15;          // col/dim group 0..15
    const int r4 = rg * 4;
    const int c4 = cg * 4;

    float m[4], l[4], acc[4][4];
#pragma unroll
    for (int i = 0; i < 4; i++) {
        m[i] = -1e30f; l[i] = 0.0f;
#pragma unroll
        for (int j = 0; j < 4; j++) acc[i][j] = 0.0f;
    }

    for (int kt = 0; kt <= qt; kt++) {
        __syncthreads();   // previous iteration done with Kst/Vs (and orders Q stores)
        for (int i = t; i < 4096; i += 256) {
            int rr = i >> 6, c = i & 63;
            float kv = Kg[((size_t)(kt * 64 + rr)) * 2048 + c];
            float vv = Vg[((size_t)(kt * 64 + rr)) * 2048 + c];
            Kst[c * FA_P + rr] = kv;
            Vs[rr * FA_P + c]  = vv;
        }
        __syncthreads();

        // scores s[i][j] = sum_d Q[r4+i][d] * K[c4+j][d]
        float s[4][4];
#pragma unroll
        for (int i = 0; i < 4; i++)
#pragma unroll
            for (int j = 0; j < 4; j++) s[i][j] = 0.0f;

#pragma unroll 8
        for (int d = 0; d < 64; d++) {
            float4 qf = *(const float4*)&Qst[d * FA_P + r4];
            float4 kf = *(const float4*)&Kst[d * FA_P + c4];
            float qa[4] = {qf.x, qf.y, qf.z, qf.w};
            float ka[4] = {kf.x, kf.y, kf.z, kf.w};
#pragma unroll
            for (int i = 0; i < 4; i++)
#pragma unroll
                for (int j = 0; j < 4; j++) s[i][j] += qa[i] * ka[j];
        }

        // causal mask (only diagonal tile needs it)
        if (kt == qt) {
#pragma unroll
            for (int i = 0; i < 4; i++)
#pragma unroll
                for (int j = 0; j < 4; j++)
                    if (c4 + j > r4 + i) s[i][j] = -1e30f;
        }

        // row max across 16-lane row group
        float mt[4];
#pragma unroll
        for (int i = 0; i < 4; i++)
            mt[i] = fmaxf(fmaxf(s[i][0], s[i][1]), fmaxf(s[i][2], s[i][3]));
#pragma unroll
        for (int off = 1; off <= 8; off <<= 1)
#pragma unroll
            for (int i = 0; i < 4; i++)
                mt[i] = fmaxf(mt[i], __shfl_xor_sync(0xffffffffu, mt[i], off));

        float p[4][4], ls[4], al[4];
#pragma unroll
        for (int i = 0; i < 4; i++) {
            float mn = fmaxf(m[i], mt[i]);
            al[i] = __expf(m[i] - mn);
            m[i]  = mn;
            ls[i] = 0.0f;
#pragma unroll
            for (int j = 0; j < 4; j++) {
                p[i][j] = __expf(s[i][j] - mn);
                ls[i] += p[i][j];
            }
        }
#pragma unroll
        for (int off = 1; off <= 8; off <<= 1)
#pragma unroll
            for (int i = 0; i < 4; i++)
                ls[i] += __shfl_xor_sync(0xffffffffu, ls[i], off);
#pragma unroll
        for (int i = 0; i < 4; i++) {
            l[i] = l[i] * al[i] + ls[i];
#pragma unroll
            for (int j = 0; j < 4; j++) acc[i][j] *= al[i];
        }

        // stage probs transposed (warp-local: row group = 16 consecutive lanes)
#pragma unroll
        for (int i = 0; i < 4; i++)
#pragma unroll
            for (int j = 0; j < 4; j++)
                Ps[(c4 + j) * FA_P + (r4 + i)] = p[i][j];
        __syncwarp();

        // PV: acc[i][j] += sum_c P[r4+i][c] * V[c][c4+j]
#pragma unroll 8
        for (int c = 0; c < 64; c++) {
            float4 pf = *(const float4*)&Ps[c * FA_P + r4];
            float4 vf = *(const float4*)&Vs[c * FA_P + c4];
            float pa[4] = {pf.x, pf.y, pf.z, pf.w};
            float va[4] = {vf.x, vf.y, vf.z, vf.w};
#pragma unroll
            for (int i = 0; i < 4; i++)
#pragma unroll
                for (int j = 0; j < 4; j++) acc[i][j] += pa[i] * va[j];
        }
        __syncwarp();  // PV reads done before next iteration's Ps overwrite
    }

    // epilogue
#pragma unroll
    for (int i = 0; i < 4; i++) {
        float inv = 1.0f / l[i];
        float4 o = make_float4(acc[i][0] * inv, acc[i][1] * inv,
                               acc[i][2] * inv, acc[i][3] * inv);
        *(float4*)&Og[(size_t)(r4 + i) * 1024 + c4] = o;
    }
}

// -------------------- launch --------------------
extern "C" void kernel_launch(void* const* d_in, const int* in_sizes, int n_in,
                              void* d_out, int out_size)
{
    const float* x    = (const float*)d_in[0];
    const float* Wdq  = (const float*)d_in[1];
    const float* Wuq  = (const float*)d_in[2];
    const float* qg   = (const float*)d_in[3];
    const float* qb   = (const float*)d_in[4];
    const float* Wdkv = (const float*)d_in[5];
    const float* Wukv = (const float*)d_in[6];
    const float* kg   = (const float*)d_in[7];
    const float* kb   = (const float*)d_in[8];
    const float* Wo   = (const float*)d_in[9];
    float* out = (float*)d_out;

    float *cdown, *cln, *Q, *KV, *O;
    cudaGetSymbolAddress((void**)&cdown, g_cdown);
    cudaGetSymbolAddress((void**)&cln,   g_cln);
    cudaGetSymbolAddress((void**)&Q,     g_Q);
    cudaGetSymbolAddress((void**)&KV,    g_KV);
    cudaGetSymbolAddress((void**)&O,     g_O);

    cudaFuncSetAttribute(flash_kernel, cudaFuncAttributeMaxDynamicSharedMemorySize, FA_SMEM);

    dim3 blk(256);

    // down projections: cdown[:, :256] = x @ W_dq ; cdown[:, 256:] = x @ W_dkv
    gemm_kernel<false><<<dim3(2, 32), blk>>>(x, Wdq,  cdown,       1024, 1024, 256,  512);
    gemm_kernel<false><<<dim3(2, 32), blk>>>(x, Wdkv, cdown + 256, 1024, 1024, 256,  512);

    // layernorm both halves
    ln_kernel<<<dim3(4096, 2), blk>>>(cdown, cln, qg, qb, kg, kb);

    // up projections
    gemm_kernel<false><<<dim3(8, 32),  blk>>>(cln,       Wuq,  Q,  256, 512, 1024, 1024);
    gemm_kernel<false><<<dim3(16, 32), blk>>>(cln + 256, Wukv, KV, 256, 512, 2048, 2048);

    // causal attention
    flash_kernel<<<dim3(32, 32), blk, FA_SMEM>>>(Q, KV, O);

    // output projection: out = O @ W_o^T
    gemm_kernel<true><<<dim3(8, 32), blk>>>(O, Wo, out, 1024, 1024, 1024, 1024);
}

// round 10
// speedup vs baseline: 1.0037x; 1.0037x over previous
#include <cuda_runtime.h>
#include <math.h>

// Problem constants
//   x: [2, 2048, 1024] -> rows M=4096
//   Q_PROJ = KV_PROJ = 256, N_HEADS=16, DH=64
// Pipeline:
//   cdown = x @ [W_dq | W_dkv]          [4096, 512]
//   cln   = LN(cdown) per 256-half      [4096, 512]
//   Q     = cln[:, :256] @ W_uq         [4096, 1024]
//   KV    = cln[:, 256:] @ W_ukv        [4096, 2048]   (K = cols 0..1023, V = 1024..2047)
//   O     = causal_attention(Q, K, V)   [4096, 1024]
//   out   = O @ W_o^T                   [4096, 1024]

// -------------------- scratch (device globals; no allocation) --------------------
__device__ float g_cdown[4096 * 512];
__device__ float g_cln  [4096 * 512];
__device__ float g_Q    [4096 * 1024];
__device__ float g_KV   [4096 * 2048];
__device__ float g_O    [4096 * 1024];

// -------------------- helpers --------------------
__device__ __forceinline__ float warp_sum32(float v) {
    v += __shfl_xor_sync(0xffffffffu, v, 16);
    v += __shfl_xor_sync(0xffffffffu, v, 8);
    v += __shfl_xor_sync(0xffffffffu, v, 4);
    v += __shfl_xor_sync(0xffffffffu, v, 2);
    v += __shfl_xor_sync(0xffffffffu, v, 1);
    return v;
}

// -------------------- generic tiled SGEMM: C[M,N] = A[M,K] @ B(K,N) --------------------
// BM=BN=128, BK=8, 256 threads, 8x8 microtile (split 4+4 halves for conflict-free LDS.128).
// TRANSB=false: B is row-major [K,N].  TRANSB=true: C = A @ B^T with B row-major [N,K].
template <bool TRANSB>
__global__ __launch_bounds__(256) void gemm_kernel(
    const float* __restrict__ A, const float* __restrict__ B, float* __restrict__ C,
    int K, int lda, int ldb, int ldc)
{
    __shared__ float As[8][128];   // As[k][m]
    __shared__ float Bs[8][128];   // Bs[k][n]

    const int t  = threadIdx.x;
    const int tx = t & 15;         // N direction
    const int ty = t >> 4;         // M direction
    const int m0 = blockIdx.y * 128;
    const int n0 = blockIdx.x * 128;

    float acc[8][8];
#pragma unroll
    for (int i = 0; i < 8; i++)
#pragma unroll
        for (int j = 0; j < 8; j++) acc[i][j] = 0.0f;

    const int am = t >> 1;            // 0..127
    const int ak = (t & 1) * 4;       // 0 or 4

    for (int k0 = 0; k0 < K; k0 += 8) {
        // load A tile (128 x 8), store transposed
        {
            float4 av = *(const float4*)&A[(size_t)(m0 + am) * lda + k0 + ak];
            As[ak + 0][am] = av.x;
            As[ak + 1][am] = av.y;
            As[ak + 2][am] = av.z;
            As[ak + 3][am] = av.w;
        }
        // load B tile (8 x 128)
        if (TRANSB) {
            const int j  = t >> 1;           // 0..127 (output col)
            const int kk = (t & 1) * 4;
            float4 bv = *(const float4*)&B[(size_t)(n0 + j) * ldb + k0 + kk];
            Bs[kk + 0][j] = bv.x;
            Bs[kk + 1][j] = bv.y;
            Bs[kk + 2][j] = bv.z;
            Bs[kk + 3][j] = bv.w;
        } else {
            const int kk = t >> 5;           // 0..7
            const int c  = (t & 31) * 4;     // 0..124
            float4 bv = *(const float4*)&B[(size_t)(k0 + kk) * ldb + n0 + c];
            *(float4*)&Bs[kk][c] = bv;
        }
        __syncthreads();

#pragma unroll
        for (int k = 0; k < 8; k++) {
            float4 a0 = *(const float4*)&As[k][ty * 4];
            float4 a1 = *(const float4*)&As[k][64 + ty * 4];
            float4 b0 = *(const float4*)&Bs[k][tx * 4];
            float4 b1 = *(const float4*)&Bs[k][64 + tx * 4];
            float a[8] = {a0.x, a0.y, a0.z, a0.w, a1.x, a1.y, a1.z, a1.w};
            float b[8] = {b0.x, b0.y, b0.z, b0.w, b1.x, b1.y, b1.z, b1.w};
#pragma unroll
            for (int i = 0; i < 8; i++)
#pragma unroll
                for (int j = 0; j < 8; j++) acc[i][j] += a[i] * b[j];
        }
        __syncthreads();
    }

    // store: rows {ty*4+i, 64+ty*4+i}, cols {tx*4+j, 64+tx*4+j}
#pragma unroll
    for (int i = 0; i < 8; i++) {
        int row = m0 + ((i < 4) ? (ty * 4 + i) : (64 + ty * 4 + (i - 4)));
        float4 c0 = make_float4(acc[i][0], acc[i][1], acc[i][2], acc[i][3]);
        float4 c1 = make_float4(acc[i][4], acc[i][5], acc[i][6], acc[i][7]);
        *(float4*)&C[(size_t)row * ldc + n0 + tx * 4]      = c0;
        *(float4*)&C[(size_t)row * ldc + n0 + 64 + tx * 4] = c1;
    }
}

// -------------------- layernorm over 256-element halves --------------------
// grid: (4096 rows, 2 halves), 256 threads
__global__ __launch_bounds__(256) void ln_kernel(
    const float* __restrict__ cd, float* __restrict__ cl,
    const float* __restrict__ qg, const float* __restrict__ qb,
    const float* __restrict__ kg, const float* __restrict__ kb)
{
    const int row  = blockIdx.x;
    const int half = blockIdx.y;
    const int tid  = threadIdx.x;
    const size_t idx = (size_t)row * 512 + half * 256 + tid;

    float v = cd[idx];

    __shared__ float red[8];
    float s = warp_sum32(v);
    if ((tid & 31) == 0) red[tid >> 5] = s;
    __syncthreads();
    float tot = 0.0f;
#pragma unroll
    for (int i = 0; i < 8; i++) tot += red[i];
    float mu = tot * (1.0f / 256.0f);
    float d  = v - mu;
    __syncthreads();

    float s2 = warp_sum32(d * d);
    if ((tid & 31) == 0) red[tid >> 5] = s2;
    __syncthreads();
    float var = 0.0f;
#pragma unroll
    for (int i = 0; i < 8; i++) var += red[i];
    var *= (1.0f / 256.0f);

    float inv = rsqrtf(var + 1e-5f);
    const float* g = half ? kg : qg;
    const float* b = half ? kb : qb;
    cl[idx] = d * inv * g[tid] + b[tid];
}

// -------------------- causal flash attention --------------------
// grid: (32 q-tiles, 32 b*h), 256 threads. BM=BN=64, DH=64.
// Thread (rg, cg): rows rg*4..+3, score cols / output dims cg*4..+3.
// smem pitch 68 (mult of 4 for float4 alignment; breaks 32-way transpose-store conflicts).
#define FA_P 68
#define FA_SMEM (4 * 64 * FA_P * 4)

__global__ __launch_bounds__(256) void flash_kernel(
    const float* __restrict__ Qb, const float* __restrict__ KVb, float* __restrict__ Ob)
{
    extern __shared__ float sm[];
    float* Qst = sm;                 // [d][r]  (transposed)
    float* Kst = sm + 64 * FA_P;     // [d][c]  (transposed)
    float* Vs  = sm + 2 * 64 * FA_P; // [c][d]
    float* Ps  = sm + 3 * 64 * FA_P; // [c][r]  (transposed probs)

    const int bh = blockIdx.y;
    const int b  = bh >> 4;
    const int h  = bh & 15;
    const int qt = blockIdx.x;

    const float* Qg = Qb  + ((size_t)(b * 2048 + qt * 64)) * 1024 + h * 64;
    const float* Kg = KVb + (size_t)b * 2048 * 2048 + h * 64;
    const float* Vg = Kg + 1024;
    float*       Og = Ob  + ((size_t)(b * 2048 + qt * 64)) * 1024 + h * 64;

    const int t = threadIdx.x;

    // load Q tile transposed, pre-scaled by 1/sqrt(64)
    for (int i = t; i < 4096; i += 256) {
        int r = i >> 6, c = i & 63;
        Qst[c * FA_P + r] = Qg[(size_t)r * 1024 + c] * 0.125f;
    }

    const int rg = t >> 4;          // row group 0..15
    const int cg = t & 15;          // col/dim group 0..15
    const int r4 = rg * 4;
    const int c4 = cg * 4;

    float m[4], l[4], acc[4][4];
#pragma unroll
    for (int i = 0; i < 4; i++) {
        m[i] = -1e30f; l[i] = 0.0f;
#pragma unroll
        for (int j = 0; j < 4; j++) acc[i][j] = 0.0f;
    }

    for (int kt = 0; kt <= qt; kt++) {
        __syncthreads();   // previous iteration done with Kst/Vs (and orders Q stores)
        for (int i = t; i < 4096; i += 256) {
            int rr = i >> 6, c = i & 63;
            float kv = Kg[((size_t)(kt * 64 + rr)) * 2048 + c];
            float vv = Vg[((size_t)(kt * 64 + rr)) * 2048 + c];
            Kst[c * FA_P + rr] = kv;
            Vs[rr * FA_P + c]  = vv;
        }
        __syncthreads();

        // scores s[i][j] = sum_d Q[r4+i][d] * K[c4+j][d]
        float s[4][4];
#pragma unroll
        for (int i = 0; i < 4; i++)
#pragma unroll
            for (int j = 0; j < 4; j++) s[i][j] = 0.0f;

#pragma unroll 8
        for (int d = 0; d < 64; d++) {
            float4 qf = *(const float4*)&Qst[d * FA_P + r4];
            float4 kf = *(const float4*)&Kst[d * FA_P + c4];
            float qa[4] = {qf.x, qf.y, qf.z, qf.w};
            float ka[4] = {kf.x, kf.y, kf.z, kf.w};
#pragma unroll
            for (int i = 0; i < 4; i++)
#pragma unroll
                for (int j = 0; j < 4; j++) s[i][j] += qa[i] * ka[j];
        }

        // causal mask (only diagonal tile needs it)
        if (kt == qt) {
#pragma unroll
            for (int i = 0; i < 4; i++)
#pragma unroll
                for (int j = 0; j < 4; j++)
                    if (c4 + j > r4 + i) s[i][j] = -1e30f;
        }

        // row max across 16-lane row group
        float mt[4];
#pragma unroll
        for (int i = 0; i < 4; i++)
            mt[i] = fmaxf(fmaxf(s[i][0], s[i][1]), fmaxf(s[i][2], s[i][3]));
#pragma unroll
        for (int off = 1; off <= 8; off <<= 1)
#pragma unroll
            for (int i = 0; i < 4; i++)
                mt[i] = fmaxf(mt[i], __shfl_xor_sync(0xffffffffu, mt[i], off));

        float p[4][4], ls[4], al[4];
#pragma unroll
        for (int i = 0; i < 4; i++) {
            float mn = fmaxf(m[i], mt[i]);
            al[i] = __expf(m[i] - mn);
            m[i]  = mn;
            ls[i] = 0.0f;
#pragma unroll
            for (int j = 0; j < 4; j++) {
                p[i][j] = __expf(s[i][j] - mn);
                ls[i] += p[i][j];
            }
        }
#pragma unroll
        for (int off = 1; off <= 8; off <<= 1)
#pragma unroll
            for (int i = 0; i < 4; i++)
                ls[i] += __shfl_xor_sync(0xffffffffu, ls[i], off);
#pragma unroll
        for (int i = 0; i < 4; i++) {
            l[i] = l[i] * al[i] + ls[i];
#pragma unroll
            for (int j = 0; j < 4; j++) acc[i][j] *= al[i];
        }

        // stage probs transposed (warp-local: row group = 16 consecutive lanes)
#pragma unroll
        for (int i = 0; i < 4; i++)
#pragma unroll
            for (int j = 0; j < 4; j++)
                Ps[(c4 + j) * FA_P + (r4 + i)] = p[i][j];
        __syncwarp();

        // PV: acc[i][j] += sum_c P[r4+i][c] * V[c][c4+j]
#pragma unroll 8
        for (int c = 0; c < 64; c++) {
            float4 pf = *(const float4*)&Ps[c * FA_P + r4];
            float4 vf = *(const float4*)&Vs[c * FA_P + c4];
            float pa[4] = {pf.x, pf.y, pf.z, pf.w};
            float va[4] = {vf.x, vf.y, vf.z, vf.w};
#pragma unroll
            for (int i = 0; i < 4; i++)
#pragma unroll
                for (int j = 0; j < 4; j++) acc[i][j] += pa[i] * va[j];
        }
        __syncwarp();  // PV reads done before next iteration's Ps overwrite
    }

    // epilogue
#pragma unroll
    for (int i = 0; i < 4; i++) {
        float inv = 1.0f / l[i];
        float4 o = make_float4(acc[i][0] * inv, acc[i][1] * inv,
                               acc[i][2] * inv, acc[i][3] * inv);
        *(float4*)&Og[(size_t)(r4 + i) * 1024 + c4] = o;
    }
}

// -------------------- launch --------------------
extern "C" void kernel_launch(void* const* d_in, const int* in_sizes, int n_in,
                              void* d_out, int out_size)
{
    const float* x    = (const float*)d_in[0];
    const float* Wdq  = (const float*)d_in[1];
    const float* Wuq  = (const float*)d_in[2];
    const float* qg   = (const float*)d_in[3];
    const float* qb   = (const float*)d_in[4];
    const float* Wdkv = (const float*)d_in[5];
    const float* Wukv = (const float*)d_in[6];
    const float* kg   = (const float*)d_in[7];
    const float* kb   = (const float*)d_in[8];
    const float* Wo   = (const float*)d_in[9];
    float* out = (float*)d_out;

    float *cdown, *cln, *Q, *KV, *O;
    cudaGetSymbolAddress((void**)&cdown, g_cdown);
    cudaGetSymbolAddress((void**)&cln,   g_cln);
    cudaGetSymbolAddress((void**)&Q,     g_Q);
    cudaGetSymbolAddress((void**)&KV,    g_KV);
    cudaGetSymbolAddress((void**)&O,     g_O);

    cudaFuncSetAttribute(flash_kernel, cudaFuncAttributeMaxDynamicSharedMemorySize, FA_SMEM);

    dim3 blk(256);

    // down projections: cdown[:, :256] = x @ W_dq ; cdown[:, 256:] = x @ W_dkv
    gemm_kernel<false><<<dim3(2, 32), blk>>>(x, Wdq,  cdown,       1024, 1024, 256,  512);
    gemm_kernel<false><<<dim3(2, 32), blk>>>(x, Wdkv, cdown + 256, 1024, 1024, 256,  512);

    // layernorm both halves
    ln_kernel<<<dim3(4096, 2), blk>>>(cdown, cln, qg, qb, kg, kb);

    // up projections
    gemm_kernel<false><<<dim3(8, 32),  blk>>>(cln,       Wuq,  Q,  256, 512, 1024, 1024);
    gemm_kernel<false><<<dim3(16, 32), blk>>>(cln + 256, Wukv, KV, 256, 512, 2048, 2048);

    // causal attention
    flash_kernel<<<dim3(32, 32), blk, FA_SMEM>>>(Q, KV, O);

    // output projection: out = O @ W_o^T
    gemm_kernel<true><<<dim3(8, 32), blk>>>(O, Wo, out, 1024, 1024, 1024, 1024);
}